// round 10
// baseline (speedup 1.0000x reference)
#include <cuda_runtime.h>
#include <cuda_bf16.h>
#include <math.h>

#define N_ROIS 128
#define BEV_H 188
#define BEV_W 188
#define BEV_C 256
#define THREADS 256
#define WARPS 8
#define FULL 0xFFFFFFFFu

__global__ void __launch_bounds__(THREADS)
vsa_fused_kernel(const float* __restrict__ points,
                 const float* __restrict__ rois,
                 const float* __restrict__ bev,
                 float* __restrict__ out,
                 int n)
{
    // ROI cache: (cx, cy, cz, radius = ||dims/2|| + 2.4)
    __shared__ float4 s_roi[N_ROIS];
    // Phase-1 -> phase-2 handoff, per warp per point
    __shared__ float4 s_wt[WARPS][32];   // bilinear weights
    __shared__ int4   s_off[WARPS][32];  // x0,x1,y0,y1 (gather points only)

    if (threadIdx.x < N_ROIS) {
        const float* rp = rois + threadIdx.x * 7;
        const float hl = rp[3] * 0.5f;
        const float hw = rp[4] * 0.5f;
        const float hh = rp[5] * 0.5f;
        const float rad = sqrtf(hl * hl + hw * hw + hh * hh) + 2.4f;
        s_roi[threadIdx.x] = make_float4(rp[0], rp[1], rp[2], rad);
    }
    __syncthreads();

    const int w    = threadIdx.x >> 5;
    const int lane = threadIdx.x & 31;
    const int p    = blockIdx.x * THREADS + threadIdx.x;
    const bool valid = p < n;

    // ---------------- Phase 1: thread-per-point argmin ----------------
    float px = 0.f, py = 0.f, pz = 0.f;
    if (valid) {
        px = points[p * 3 + 0];
        py = points[p * 3 + 1];
        pz = points[p * 3 + 2];
    }

    float best = INFINITY;
    int bidx = 0;
    #pragma unroll 4
    for (int r = 0; r < N_ROIS; r++) {
        const float4 q = s_roi[r];     // warp-broadcast LDS.128
        const float dx = px - q.x;
        const float dy = py - q.y;
        const float dz = pz - q.z;
        const float d2 = dx * dx + dy * dy + dz * dz;
        if (d2 < best) { best = d2; bidx = r; }   // '<' -> first occurrence
    }
    const float rad  = s_roi[bidx].w;
    const bool  mask = valid && (sqrtf(best) < rad);

    if (mask) {
        // bit-faithful coords: two fp32 divides, floor, clamp
        const float xi = (px - 0.0f)   / 0.05f / 8.0f;
        const float yi = (py - -40.0f) / 0.05f / 8.0f;
        const int xf = (int)floorf(xi);
        const int yf = (int)floorf(yi);
        const int x0 = min(max(xf,     0), BEV_W - 1);
        const int x1 = min(max(xf + 1, 0), BEV_W - 1);
        const int y0 = min(max(yf,     0), BEV_H - 1);
        const int y1 = min(max(yf + 1, 0), BEV_H - 1);
        const float x0f = (float)x0, x1f = (float)x1;
        const float y0f = (float)y0, y1f = (float)y1;
        float4 wt;
        wt.x = (x1f - xi) * (y1f - yi);   // wa
        wt.y = (x1f - xi) * (yi - y0f);   // wb
        wt.z = (xi - x0f) * (y1f - yi);   // wc
        wt.w = (xi - x0f) * (yi - y0f);   // wd
        s_wt[w][lane]  = wt;
        s_off[w][lane] = make_int4(x0, x1, y0, y1);
    }

    // warp-wide classification (all 32 lanes participate)
    unsigned zmask = __ballot_sync(FULL, valid && !mask);  // zero-fill points
    unsigned gmask = __ballot_sync(FULL, mask);            // gather points
    __syncwarp();

    const int pbase = blockIdx.x * THREADS + w * 32;

    // ---------------- Phase 2a: dependency-free zero-store stream ----------------
    {
        const float4 z = make_float4(0.f, 0.f, 0.f, 0.f);
        unsigned m = zmask;
        while (m) {
            const int j = __ffs(m) - 1;
            m &= m - 1;
            float4* op = reinterpret_cast<float4*>(out + (size_t)(pbase + j) * BEV_C);
            __stcs(op + lane,      z);
            __stcs(op + lane + 32, z);
        }
    }

    // ---------------- Phase 2b: gather points only (MLP=8 each) ----------------
    {
        unsigned m = gmask;
        while (m) {
            const int j = __ffs(m) - 1;
            m &= m - 1;

            const int4   o  = s_off[w][j];   // warp-broadcast
            const float4 wv = s_wt[w][j];    // warp-broadcast

            const float4* A  = reinterpret_cast<const float4*>(bev + ((size_t)o.z * BEV_W + o.x) * BEV_C);
            const float4* B  = reinterpret_cast<const float4*>(bev + ((size_t)o.w * BEV_W + o.x) * BEV_C);
            const float4* Cc = reinterpret_cast<const float4*>(bev + ((size_t)o.z * BEV_W + o.y) * BEV_C);
            const float4* D  = reinterpret_cast<const float4*>(bev + ((size_t)o.w * BEV_W + o.y) * BEV_C);

            // all 8 corner loads issued before any FMA
            const float4 a0 = __ldcg(A  + lane);
            const float4 b0 = __ldcg(B  + lane);
            const float4 c0 = __ldcg(Cc + lane);
            const float4 d0 = __ldcg(D  + lane);
            const float4 a1 = __ldcg(A  + lane + 32);
            const float4 b1 = __ldcg(B  + lane + 32);
            const float4 c1 = __ldcg(Cc + lane + 32);
            const float4 d1 = __ldcg(D  + lane + 32);

            float4 o0, o1;
            o0.x = a0.x * wv.x + b0.x * wv.y + c0.x * wv.z + d0.x * wv.w;
            o0.y = a0.y * wv.x + b0.y * wv.y + c0.y * wv.z + d0.y * wv.w;
            o0.z = a0.z * wv.x + b0.z * wv.y + c0.z * wv.z + d0.z * wv.w;
            o0.w = a0.w * wv.x + b0.w * wv.y + c0.w * wv.z + d0.w * wv.w;
            o1.x = a1.x * wv.x + b1.x * wv.y + c1.x * wv.z + d1.x * wv.w;
            o1.y = a1.y * wv.x + b1.y * wv.y + c1.y * wv.z + d1.y * wv.w;
            o1.z = a1.z * wv.x + b1.z * wv.y + c1.z * wv.z + d1.z * wv.w;
            o1.w = a1.w * wv.x + b1.w * wv.y + c1.w * wv.z + d1.w * wv.w;

            float4* op = reinterpret_cast<float4*>(out + (size_t)(pbase + j) * BEV_C);
            __stcs(op + lane,      o0);
            __stcs(op + lane + 32, o1);
        }
    }
}

extern "C" void kernel_launch(void* const* d_in, const int* in_sizes, int n_in,
                              void* d_out, int out_size)
{
    const float* points = (const float*)d_in[0];
    const float* rois   = (const float*)d_in[1];
    const float* bev    = (const float*)d_in[2];
    float* out = (float*)d_out;

    const int n = in_sizes[0] / 3;
    const int blocks = (n + THREADS - 1) / THREADS;
    vsa_fused_kernel<<<blocks, THREADS>>>(points, rois, bev, out, n);
}

// round 13
// speedup vs baseline: 1.0294x; 1.0294x over previous
#include <cuda_runtime.h>
#include <cuda_bf16.h>
#include <cstdint>
#include <math.h>

#define N_ROIS 128
#define BEV_H 188
#define BEV_W 188
#define BEV_C 256
#define THREADS 256
#define WARPS 8
#define FULL 0xFFFFFFFFu
#define ZROWS 8                       // zero buffer covers up to 8 output rows
#define ROW_BYTES (BEV_C * 4)         // 1024

__global__ void __launch_bounds__(THREADS)
vsa_fused_kernel(const float* __restrict__ points,
                 const float* __restrict__ rois,
                 const float* __restrict__ bev,
                 float* __restrict__ out,
                 int n)
{
    // ROI cache: (cx, cy, cz, radius = ||dims/2|| + 2.4)
    __shared__ float4 s_roi[N_ROIS];
    __shared__ float4 s_wt[WARPS][32];            // weights (gather pts)
    __shared__ int4   s_off[WARPS][32];           // corners (gather pts)
    __shared__ alignas(128) float4 s_zero[ZROWS * BEV_C / 4];  // 8 KB of zeros

    // init ROI cache + zero buffer
    if (threadIdx.x < N_ROIS) {
        const float* rp = rois + threadIdx.x * 7;
        const float hl = rp[3] * 0.5f;
        const float hw = rp[4] * 0.5f;
        const float hh = rp[5] * 0.5f;
        const float rad = sqrtf(hl * hl + hw * hw + hh * hh) + 2.4f;
        s_roi[threadIdx.x] = make_float4(rp[0], rp[1], rp[2], rad);
    }
    {
        const float4 z = make_float4(0.f, 0.f, 0.f, 0.f);
        #pragma unroll
        for (int i = threadIdx.x; i < ZROWS * BEV_C / 4; i += THREADS)
            s_zero[i] = z;
    }
    // make zero buffer visible to the async (TMA) proxy before any bulk store
    asm volatile("fence.proxy.async.shared::cta;" ::: "memory");
    __syncthreads();

    const int w    = threadIdx.x >> 5;
    const int lane = threadIdx.x & 31;
    const int p    = blockIdx.x * THREADS + threadIdx.x;
    const bool valid = p < n;

    // ---------------- Phase 1: thread-per-point argmin ----------------
    float px = 0.f, py = 0.f, pz = 0.f;
    if (valid) {
        px = points[p * 3 + 0];
        py = points[p * 3 + 1];
        pz = points[p * 3 + 2];
    }

    float best = INFINITY;
    int bidx = 0;
    #pragma unroll 4
    for (int r = 0; r < N_ROIS; r++) {
        const float4 q = s_roi[r];     // warp-broadcast LDS.128
        const float dx = px - q.x;
        const float dy = py - q.y;
        const float dz = pz - q.z;
        const float d2 = dx * dx + dy * dy + dz * dz;
        if (d2 < best) { best = d2; bidx = r; }   // '<' -> first occurrence
    }
    const float rad  = s_roi[bidx].w;
    const bool  mask = valid && (sqrtf(best) < rad);

    if (mask) {
        // bit-faithful coords: two fp32 divides, floor, clamp
        const float xi = (px - 0.0f)   / 0.05f / 8.0f;
        const float yi = (py - -40.0f) / 0.05f / 8.0f;
        const int xf = (int)floorf(xi);
        const int yf = (int)floorf(yi);
        const int x0 = min(max(xf,     0), BEV_W - 1);
        const int x1 = min(max(xf + 1, 0), BEV_W - 1);
        const int y0 = min(max(yf,     0), BEV_H - 1);
        const int y1 = min(max(yf + 1, 0), BEV_H - 1);
        const float x0f = (float)x0, x1f = (float)x1;
        const float y0f = (float)y0, y1f = (float)y1;
        float4 wt;
        wt.x = (x1f - xi) * (y1f - yi);
        wt.y = (x1f - xi) * (yi - y0f);
        wt.z = (xi - x0f) * (y1f - yi);
        wt.w = (xi - x0f) * (yi - y0f);
        s_wt[w][lane]  = wt;
        s_off[w][lane] = make_int4(x0, x1, y0, y1);
    }

    const unsigned zmask = __ballot_sync(FULL, valid && !mask);
    const unsigned gmask = __ballot_sync(FULL, mask);
    __syncwarp();

    const int pbase = blockIdx.x * THREADS + w * 32;

    // ---------- Phase 2a: zero rows via TMA bulk stores (lane 0 only) ----------
    if (lane == 0 && zmask) {
        const unsigned int zsrc =
            (unsigned int)__cvta_generic_to_shared(s_zero);
        unsigned m = zmask;
        while (m) {
            const int j = __ffs(m) - 1;
            // length of consecutive-zero run starting at j (cap = ZROWS)
            int len = 1;
            while (len < ZROWS && (j + len) < 32 && ((m >> (j + len)) & 1u)) len++;
            // clear the run bits
            const unsigned runbits = ((len == 32) ? 0xFFFFFFFFu : ((1u << len) - 1u)) << j;
            m &= ~runbits;

            float* gdst = out + (size_t)(pbase + j) * BEV_C;
            const unsigned bytes = (unsigned)(len * ROW_BYTES);
            asm volatile(
                "cp.async.bulk.global.shared::cta.bulk_group [%0], [%1], %2;"
                :: "l"(gdst), "r"(zsrc), "r"(bytes) : "memory");
        }
        asm volatile("cp.async.bulk.commit_group;" ::: "memory");
    }

    // ---------- Phase 2b: gather points (warp-per-point, MLP=8) ----------
    {
        unsigned m = gmask;
        while (m) {
            const int j = __ffs(m) - 1;
            m &= m - 1;

            const int4   o  = s_off[w][j];   // warp-broadcast
            const float4 wv = s_wt[w][j];    // warp-broadcast

            const float4* A  = reinterpret_cast<const float4*>(bev + ((size_t)o.z * BEV_W + o.x) * BEV_C);
            const float4* B  = reinterpret_cast<const float4*>(bev + ((size_t)o.w * BEV_W + o.x) * BEV_C);
            const float4* Cc = reinterpret_cast<const float4*>(bev + ((size_t)o.z * BEV_W + o.y) * BEV_C);
            const float4* D  = reinterpret_cast<const float4*>(bev + ((size_t)o.w * BEV_W + o.y) * BEV_C);

            const float4 a0 = __ldcg(A  + lane);
            const float4 b0 = __ldcg(B  + lane);
            const float4 c0 = __ldcg(Cc + lane);
            const float4 d0 = __ldcg(D  + lane);
            const float4 a1 = __ldcg(A  + lane + 32);
            const float4 b1 = __ldcg(B  + lane + 32);
            const float4 c1 = __ldcg(Cc + lane + 32);
            const float4 d1 = __ldcg(D  + lane + 32);

            float4 o0, o1;
            o0.x = a0.x * wv.x + b0.x * wv.y + c0.x * wv.z + d0.x * wv.w;
            o0.y = a0.y * wv.x + b0.y * wv.y + c0.y * wv.z + d0.y * wv.w;
            o0.z = a0.z * wv.x + b0.z * wv.y + c0.z * wv.z + d0.z * wv.w;
            o0.w = a0.w * wv.x + b0.w * wv.y + c0.w * wv.z + d0.w * wv.w;
            o1.x = a1.x * wv.x + b1.x * wv.y + c1.x * wv.z + d1.x * wv.w;
            o1.y = a1.y * wv.x + b1.y * wv.y + c1.y * wv.z + d1.y * wv.w;
            o1.z = a1.z * wv.x + b1.z * wv.y + c1.z * wv.z + d1.z * wv.w;
            o1.w = a1.w * wv.x + b1.w * wv.y + c1.w * wv.z + d1.w * wv.w;

            float4* op = reinterpret_cast<float4*>(out + (size_t)(pbase + j) * BEV_C);
            __stcs(op + lane,      o0);
            __stcs(op + lane + 32, o1);
        }
    }

    // drain bulk stores before exit (smem zero buffer must outlive TMA reads)
    if (lane == 0 && zmask) {
        asm volatile("cp.async.bulk.wait_group 0;" ::: "memory");
    }
    __syncthreads();
}

extern "C" void kernel_launch(void* const* d_in, const int* in_sizes, int n_in,
                              void* d_out, int out_size)
{
    const float* points = (const float*)d_in[0];
    const float* rois   = (const float*)d_in[1];
    const float* bev    = (const float*)d_in[2];
    float* out = (float*)d_out;

    const int n = in_sizes[0] / 3;
    const int blocks = (n + THREADS - 1) / THREADS;
    vsa_fused_kernel<<<blocks, THREADS>>>(points, rois, bev, out, n);
}

// round 14
// speedup vs baseline: 1.1239x; 1.0918x over previous
#include <cuda_runtime.h>
#include <cuda_bf16.h>
#include <cstdint>
#include <math.h>

#define N_ROIS 128
#define BEV_H 188
#define BEV_W 188
#define BEV_C 256
#define THREADS 256
#define FULL 0xFFFFFFFFu
#define MAXN 262144

// per-point params (static scratch; no runtime allocation)
__device__ int4   g_off[MAXN];   // x0,x1,y0,y1 ; x0=-1 -> zero row
__device__ float4 g_wt[MAXN];    // bilinear weights

// ================= kernel 1: thread-per-point argmin + params =================
__global__ void __launch_bounds__(THREADS)
k_phase1(const float* __restrict__ points,
         const float* __restrict__ rois, int n)
{
    __shared__ float4 s_roi[N_ROIS];   // (cx, cy, cz, ||dims/2||+2.4)

    if (threadIdx.x < N_ROIS) {
        const float* rp = rois + threadIdx.x * 7;
        const float hl = rp[3] * 0.5f;
        const float hw = rp[4] * 0.5f;
        const float hh = rp[5] * 0.5f;
        const float rad = sqrtf(hl * hl + hw * hw + hh * hh) + 2.4f;
        s_roi[threadIdx.x] = make_float4(rp[0], rp[1], rp[2], rad);
    }
    __syncthreads();

    const int p = blockIdx.x * THREADS + threadIdx.x;
    if (p >= n) return;

    const float px = points[p * 3 + 0];
    const float py = points[p * 3 + 1];
    const float pz = points[p * 3 + 2];

    float best = INFINITY;
    int bidx = 0;
    #pragma unroll 4
    for (int r = 0; r < N_ROIS; r++) {
        const float4 q = s_roi[r];     // warp-broadcast LDS.128
        const float dx = px - q.x;
        const float dy = py - q.y;
        const float dz = pz - q.z;
        const float d2 = dx * dx + dy * dy + dz * dz;
        if (d2 < best) { best = d2; bidx = r; }   // '<' -> first occurrence
    }
    const bool mask = sqrtf(best) < s_roi[bidx].w;

    if (!mask) {
        g_off[p] = make_int4(-1, 0, 0, 0);
        return;
    }

    // bit-faithful coords: two fp32 divides, floor, clamp
    const float xi = (px - 0.0f)   / 0.05f / 8.0f;
    const float yi = (py - -40.0f) / 0.05f / 8.0f;
    const int xf = (int)floorf(xi);
    const int yf = (int)floorf(yi);
    const int x0 = min(max(xf,     0), BEV_W - 1);
    const int x1 = min(max(xf + 1, 0), BEV_W - 1);
    const int y0 = min(max(yf,     0), BEV_H - 1);
    const int y1 = min(max(yf + 1, 0), BEV_H - 1);

    const float x0f = (float)x0, x1f = (float)x1;
    const float y0f = (float)y0, y1f = (float)y1;
    float4 wt;
    wt.x = (x1f - xi) * (y1f - yi);   // wa
    wt.y = (x1f - xi) * (yi - y0f);   // wb
    wt.z = (xi - x0f) * (y1f - yi);   // wc
    wt.w = (xi - x0f) * (yi - y0f);   // wd

    g_wt[p]  = wt;
    g_off[p] = make_int4(x0, x1, y0, y1);
}

// ================= kernel 2: warp-per-point (massive oversubscription) =========
__global__ void __launch_bounds__(THREADS)
k_phase2(const float* __restrict__ bev, float* __restrict__ out, int n)
{
    const int lane = threadIdx.x & 31;
    const int p    = blockIdx.x * (THREADS / 32) + (threadIdx.x >> 5);
    if (p >= n) return;

    const int4 o = g_off[p];               // warp-broadcast LDG.128
    float4* op = reinterpret_cast<float4*>(out + (size_t)p * BEV_C);

    if (o.x < 0) {
        const float4 z = make_float4(0.f, 0.f, 0.f, 0.f);
        __stcs(op + lane,      z);
        __stcs(op + lane + 32, z);
        return;
    }

    const float4 wv = g_wt[p];             // warp-broadcast LDG.128

    const float4* A  = reinterpret_cast<const float4*>(bev + ((size_t)o.z * BEV_W + o.x) * BEV_C);
    const float4* B  = reinterpret_cast<const float4*>(bev + ((size_t)o.w * BEV_W + o.x) * BEV_C);
    const float4* Cc = reinterpret_cast<const float4*>(bev + ((size_t)o.z * BEV_W + o.y) * BEV_C);
    const float4* D  = reinterpret_cast<const float4*>(bev + ((size_t)o.w * BEV_W + o.y) * BEV_C);

    // all 8 corner loads issued before FMAs; latency hidden by 21-wave grid
    const float4 a0 = __ldcg(A  + lane);
    const float4 b0 = __ldcg(B  + lane);
    const float4 c0 = __ldcg(Cc + lane);
    const float4 d0 = __ldcg(D  + lane);
    const float4 a1 = __ldcg(A  + lane + 32);
    const float4 b1 = __ldcg(B  + lane + 32);
    const float4 c1 = __ldcg(Cc + lane + 32);
    const float4 d1 = __ldcg(D  + lane + 32);

    float4 o0, o1;
    o0.x = a0.x * wv.x + b0.x * wv.y + c0.x * wv.z + d0.x * wv.w;
    o0.y = a0.y * wv.x + b0.y * wv.y + c0.y * wv.z + d0.y * wv.w;
    o0.z = a0.z * wv.x + b0.z * wv.y + c0.z * wv.z + d0.z * wv.w;
    o0.w = a0.w * wv.x + b0.w * wv.y + c0.w * wv.z + d0.w * wv.w;
    o1.x = a1.x * wv.x + b1.x * wv.y + c1.x * wv.z + d1.x * wv.w;
    o1.y = a1.y * wv.x + b1.y * wv.y + c1.y * wv.z + d1.y * wv.w;
    o1.z = a1.z * wv.x + b1.z * wv.y + c1.z * wv.z + d1.z * wv.w;
    o1.w = a1.w * wv.x + b1.w * wv.y + c1.w * wv.z + d1.w * wv.w;

    __stcs(op + lane,      o0);
    __stcs(op + lane + 32, o1);
}

extern "C" void kernel_launch(void* const* d_in, const int* in_sizes, int n_in,
                              void* d_out, int out_size)
{
    const float* points = (const float*)d_in[0];
    const float* rois   = (const float*)d_in[1];
    const float* bev    = (const float*)d_in[2];
    float* out = (float*)d_out;

    const int n = in_sizes[0] / 3;   // n <= MAXN

    k_phase1<<<(n + THREADS - 1) / THREADS, THREADS>>>(points, rois, n);

    const int wpb = THREADS / 32;    // 8 points per block
    k_phase2<<<(n + wpb - 1) / wpb, THREADS>>>(bev, out, n);
}